// round 13
// baseline (speedup 1.0000x reference)
#include <cuda_runtime.h>
#include <cuda_bf16.h>
#include <math.h>
#include <stdint.h>

// Problem constants
#define BB 64      // batch
#define TT 256     // time steps
#define DD 1024    // input dim
#define HH 1024    // hidden dim
#define LL 4       // layers
#define GG 4096    // 4*H gate width
#define MM (TT*BB) // 16384 rows of the big GEMM
#define NBLK 128   // persistent grid size for recurrence

// ---------------------------------------------------------------------------
// Scratch (static device globals; no runtime allocation allowed)
// ---------------------------------------------------------------------------
__device__ float g_gx[(size_t)MM * GG];              // [T*B, 4H] gate pre-activations
__device__ __nv_bfloat16 g_ahi[(size_t)MM * DD];     // activations hi, [m][k]
__device__ __nv_bfloat16 g_alo[(size_t)MM * DD];     // activations lo
__device__ __nv_bfloat16 g_wthi[(size_t)GG * DD];    // Wx^T hi, [n][k]
__device__ __nv_bfloat16 g_wtlo[(size_t)GG * DD];    // Wx^T lo
__device__ __nv_bfloat16 g_whthi[(size_t)GG * HH];   // Wh^T hi, [n][k]
__device__ __nv_bfloat16 g_whtlo[(size_t)GG * HH];   // Wh^T lo
__device__ __nv_bfloat16 g_hbhi[2][BB][HH];          // h double buffer, hi
__device__ __nv_bfloat16 g_hblo[2][BB][HH];          // h double buffer, lo
__device__ unsigned g_hflag[NBLK];                   // per-block h-publish epochs

// ---------------------------------------------------------------------------
// Helpers
// ---------------------------------------------------------------------------
__device__ __forceinline__ void bsplit(float v, __nv_bfloat16& hi, __nv_bfloat16& lo) {
    hi = __float2bfloat16(v);
    lo = __float2bfloat16(v - __bfloat162float(hi));
}
__device__ __forceinline__ uint32_t smem_u32(const void* p) {
    uint32_t a;
    asm("{ .reg .u64 t; cvta.to.shared.u64 t, %1; cvt.u32.u64 %0, t; }" : "=r"(a) : "l"(p));
    return a;
}
__device__ __forceinline__ void ldsm4(uint32_t* r, uint32_t addr) {
    asm volatile("ldmatrix.sync.aligned.m8n8.x4.shared.b16 {%0,%1,%2,%3}, [%4];"
                 : "=r"(r[0]), "=r"(r[1]), "=r"(r[2]), "=r"(r[3]) : "r"(addr));
}
__device__ __forceinline__ void mma_bf16(float* d, const uint32_t* a,
                                         uint32_t b0, uint32_t b1) {
    asm volatile(
        "mma.sync.aligned.m16n8k16.row.col.f32.bf16.bf16.f32 "
        "{%0,%1,%2,%3},{%4,%5,%6,%7},{%8,%9},{%0,%1,%2,%3};"
        : "+f"(d[0]), "+f"(d[1]), "+f"(d[2]), "+f"(d[3])
        : "r"(a[0]), "r"(a[1]), "r"(a[2]), "r"(a[3]), "r"(b0), "r"(b1));
}
#define CP16(d, s) asm volatile("cp.async.cg.shared.global [%0], [%1], 16;" \
                                :: "r"(d), "l"(s) : "memory")
#define CP_COMMIT() asm volatile("cp.async.commit_group;" ::: "memory")
#define CP_WAIT1()  asm volatile("cp.async.wait_group 1;" ::: "memory")
#define CP_WAIT0()  asm volatile("cp.async.wait_group 0;" ::: "memory")

// Dataflow flag wait/publish (release/acquire, gpu scope)
__device__ __forceinline__ void wait_flag(int i, unsigned tgt) {
    unsigned v;
    do {
        asm volatile("ld.acquire.gpu.b32 %0, [%1];"
                     : "=r"(v) : "l"(g_hflag + i) : "memory");
    } while (v < tgt);
}

// ---------------------------------------------------------------------------
// prep_x: x [B,T,D] fp32 -> g_ahi/g_alo [m=t*B+b][k] bf16 hi/lo.
// Also resets the dataflow flags (this is the first node of every replay).
// ---------------------------------------------------------------------------
__global__ __launch_bounds__(256) void prep_x_kernel(const float* __restrict__ x) {
    if (blockIdx.x == 0 && threadIdx.x < NBLK) g_hflag[threadIdx.x] = 0u;
    size_t id = (size_t)blockIdx.x * 256 + threadIdx.x;   // float4 index
    int m = (int)(id >> 8);
    int d = (int)(id & 255) * 4;
    int b = m & (BB - 1), t = m >> 6;
    float4 v = *(const float4*)(x + ((size_t)b * TT + t) * DD + d);
    __nv_bfloat16 h0, h1, h2, h3, l0, l1, l2, l3;
    bsplit(v.x, h0, l0); bsplit(v.y, h1, l1);
    bsplit(v.z, h2, l2); bsplit(v.w, h3, l3);
    size_t o = (size_t)m * DD + d;
    *(__nv_bfloat162*)&g_ahi[o]     = __nv_bfloat162(h0, h1);
    *(__nv_bfloat162*)&g_ahi[o + 2] = __nv_bfloat162(h2, h3);
    *(__nv_bfloat162*)&g_alo[o]     = __nv_bfloat162(l0, l1);
    *(__nv_bfloat162*)&g_alo[o + 2] = __nv_bfloat162(l2, l3);
}

// ---------------------------------------------------------------------------
// prep_wt: W [1024 k][4096 n] fp32 -> W^T hi/lo [n][k] bf16 (transpose+split)
// sel=0 -> g_wthi/g_wtlo (Wx), sel=1 -> g_whthi/g_whtlo (Wh)
// ---------------------------------------------------------------------------
__global__ __launch_bounds__(256) void prep_wt_kernel(const float* __restrict__ W,
                                                      int sel) {
    __shared__ float tile[32][33];
    __nv_bfloat16* hi = sel ? g_whthi : g_wthi;
    __nv_bfloat16* lo = sel ? g_whtlo : g_wtlo;
    int n0 = blockIdx.x * 32, k0 = blockIdx.y * 32;
    int ty = threadIdx.x >> 5, tx = threadIdx.x & 31;
#pragma unroll
    for (int i = 0; i < 4; ++i) {
        int kk = ty + i * 8;
        tile[kk][tx] = W[(size_t)(k0 + kk) * GG + n0 + tx];
    }
    __syncthreads();
#pragma unroll
    for (int i = 0; i < 4; ++i) {
        int a = ty + i * 8;                 // local n
        float v = tile[tx][a];
        __nv_bfloat16 h, l; bsplit(v, h, l);
        size_t o = (size_t)(n0 + a) * DD + k0 + tx;
        hi[o] = h;
        lo[o] = l;
    }
}

// ---------------------------------------------------------------------------
// Tensor-core input GEMM via mma.sync (HMMA), 3-term bf16 split.
// Block tile 128x128, 8 warps x (32x64), k-chunks of 64, cp.async pipelined.
// ---------------------------------------------------------------------------
#define G_ARR  (128 * 72)           // halves per array
#define G_BUFH (4 * G_ARR)          // halves per buffer (Ahi,Alo,Bhi,Blo)
#define G_SMEM (2 * G_BUFH * 2)     // bytes (double buffered) = 147456

__global__ __launch_bounds__(256) void gemm_tc_kernel(const float* __restrict__ bias) {
    extern __shared__ char sm[];
    uint32_t sbase = smem_u32(sm);
    const int tid = threadIdx.x, lane = tid & 31, wid = tid >> 5;
    const int wm = wid >> 1, wn = wid & 1;
    const int m0 = blockIdx.y * 128, n0 = blockIdx.x * 128;

    float acc[2][8][4];
#pragma unroll
    for (int f = 0; f < 2; ++f)
#pragma unroll
        for (int q = 0; q < 8; ++q)
#pragma unroll
            for (int e = 0; e < 4; ++e) acc[f][q][e] = 0.0f;

    const uint32_t lrow = lane & 15, lcolq = (lane >> 4) * 8;

#define G_STAGE(kc) do {                                                      \
    uint32_t dstb = sbase + ((kc) & 1) * (G_BUFH * 2);                        \
    _Pragma("unroll")                                                         \
    for (int i = 0; i < 4; ++i) {                                             \
        int idx = tid + i * 256;                                              \
        int row = idx >> 3, q = idx & 7;                                      \
        size_t ga = (size_t)(m0 + row) * DD + (kc) * 64 + q * 8;              \
        size_t gb = (size_t)(n0 + row) * DD + (kc) * 64 + q * 8;              \
        uint32_t off = (uint32_t)(row * 72 + q * 8) * 2;                      \
        CP16(dstb + 0 * (G_ARR * 2) + off, g_ahi + ga);                       \
        CP16(dstb + 1 * (G_ARR * 2) + off, g_alo + ga);                       \
        CP16(dstb + 2 * (G_ARR * 2) + off, g_wthi + gb);                      \
        CP16(dstb + 3 * (G_ARR * 2) + off, g_wtlo + gb);                      \
    }                                                                         \
} while (0)

    G_STAGE(0); CP_COMMIT();

    for (int kc = 0; kc < 16; ++kc) {
        if (kc < 15) { G_STAGE(kc + 1); CP_COMMIT(); CP_WAIT1(); }
        else         { CP_WAIT0(); }
        __syncthreads();

        uint32_t bufb = sbase + (kc & 1) * (G_BUFH * 2);
#pragma unroll
        for (int s = 0; s < 4; ++s) {
            uint32_t koff = (s * 16 + lcolq) * 2;
            uint32_t ahi[2][4], alo[2][4];
#pragma unroll
            for (int f = 0; f < 2; ++f) {
                uint32_t a = bufb + (uint32_t)((wm * 32 + f * 16 + lrow) * 72) * 2 + koff;
                ldsm4(ahi[f], a);
                ldsm4(alo[f], a + G_ARR * 2);
            }
#pragma unroll
            for (int q = 0; q < 4; ++q) {
                uint32_t b = bufb + 2 * (G_ARR * 2)
                           + (uint32_t)((wn * 64 + q * 16 + lrow) * 72) * 2 + koff;
                uint32_t bh[4], bl[4];
                ldsm4(bh, b);
                ldsm4(bl, b + G_ARR * 2);
#pragma unroll
                for (int f = 0; f < 2; ++f) {
                    mma_bf16(acc[f][2 * q],     ahi[f], bh[0], bh[2]);
                    mma_bf16(acc[f][2 * q + 1], ahi[f], bh[1], bh[3]);
                    mma_bf16(acc[f][2 * q],     ahi[f], bl[0], bl[2]);
                    mma_bf16(acc[f][2 * q + 1], ahi[f], bl[1], bl[3]);
                    mma_bf16(acc[f][2 * q],     alo[f], bh[0], bh[2]);
                    mma_bf16(acc[f][2 * q + 1], alo[f], bh[1], bh[3]);
                }
            }
        }
        __syncthreads();
    }

    // epilogue: bias add + store
#pragma unroll
    for (int f = 0; f < 2; ++f) {
        int row = m0 + wm * 32 + f * 16 + (lane >> 2);
#pragma unroll
        for (int q = 0; q < 8; ++q) {
            int col = n0 + wn * 64 + q * 8 + (lane & 3) * 2;
            float2 bv = *(const float2*)&bias[col];
            *(float2*)&g_gx[(size_t)row * GG + col] =
                make_float2(acc[f][q][0] + bv.x, acc[f][q][1] + bv.y);
            *(float2*)&g_gx[(size_t)(row + 8) * GG + col] =
                make_float2(acc[f][q][2] + bv.x, acc[f][q][3] + bv.y);
        }
    }
#undef G_STAGE
}

// ---------------------------------------------------------------------------
// Persistent tensor-core recurrence, 512 threads (16 warps = 2m x 2n x 4k).
// Block b owns 8 hidden cols (j0h=b*8) -> 32 gate cols. K-chunks of 128
// (8 chunks/step), double-buffered cp.async, partials [4][64][36].
// NO grid barrier: per-block dataflow flags. Consumer thread staging h cols
// [kc*128+q*8, +8) waits only on flag[kc*16+q] (the producing block).
// Producer publishes flag[bid] = ebase+t+1 after writing h(t+1) (fence +
// release store). Max skew 1 step; double-buffered h tolerates it.
// One __syncthreads per k-chunk (wait0 -> sync -> stage next -> compute).
// ---------------------------------------------------------------------------
#define R_ROW  136                          // halves per smem row (128+8)
#define R_AHI  0
#define R_ALO  (64 * R_ROW)
#define R_BHI  (128 * R_ROW)
#define R_BLO  (160 * R_ROW)
#define R_BUFH (192 * R_ROW)                // 26112 halves = 52224 B per buffer
#define R_PART_OFF (2 * R_BUFH * 2)         // 104448 B
#define R_CSM_OFF  (R_PART_OFF + 4 * 64 * 36 * 4)   // +36864 = 141312
#define R_SMEM     (R_CSM_OFF + 64 * 8 * 4)         // 143360 B

__global__ __launch_bounds__(512) void layer_recur_kernel(
    float* __restrict__ outp, int is_last, int ebase)
{
    extern __shared__ char sm[];
    float* part = (float*)(sm + R_PART_OFF);    // [4][64][36]
    float* csm  = (float*)(sm + R_CSM_OFF);     // [64][8]
    uint32_t sbase = smem_u32(sm);

    const int tid = threadIdx.x, lane = tid & 31, wid = tid >> 5;
    const int kh = wid & 3, wn = (wid >> 2) & 1, wm = (wid >> 3) & 1;
    const int j0h = blockIdx.x * 8;

    const uint32_t lrow = lane & 15, lcolq = (lane >> 4) * 8;
    const int er = tid >> 3, ec = tid & 7;      // 1 gate element per thread

    // zero cell state (512 threads cover 64x8 exactly)
    csm[tid] = 0.0f;
    __syncthreads();

    for (int t = 0; t < TT; ++t) {
        const unsigned tgt = (unsigned)(ebase + t);   // h(t) publish epoch

        // prefetch input-side gates (1 scalar per gate chunk per thread)
        float gxv[4];
        {
            size_t base = ((size_t)t * BB + er) * GG + j0h + ec;
#pragma unroll
            for (int c = 0; c < 4; ++c)
                gxv[c] = g_gx[base + (size_t)c * 1024];
        }

        float acc[2][2][4];
#pragma unroll
        for (int f = 0; f < 2; ++f)
#pragma unroll
            for (int n = 0; n < 2; ++n)
#pragma unroll
                for (int e = 0; e < 4; ++e) acc[f][n][e] = 0.0f;

        if (t > 0) {
            const __nv_bfloat16* hhi = &g_hbhi[t & 1][0][0];
            const __nv_bfloat16* hlo = &g_hblo[t & 1][0][0];

#define R_STAGE(kc) do {                                                      \
    uint32_t dstb = sbase + ((kc) & 1) * (R_BUFH * 2);                        \
    int q = tid & 15;                                                         \
    wait_flag((kc) * 16 + q, tgt);                                            \
    _Pragma("unroll")                                                         \
    for (int i = 0; i < 2; ++i) {                                             \
        int row = (tid + i * 512) >> 4;                                       \
        size_t gs = (size_t)row * HH + (kc) * 128 + q * 8;                    \
        uint32_t off = (uint32_t)(row * R_ROW + q * 8) * 2;                   \
        CP16(dstb + R_AHI * 2 + off, hhi + gs);                               \
        CP16(dstb + R_ALO * 2 + off, hlo + gs);                               \
    }                                                                         \
    {                                                                         \
        int row = tid >> 4;                                                   \
        int gc = (row >> 3) * 1024 + j0h + (row & 7);                         \
        size_t gs = (size_t)gc * HH + (kc) * 128 + q * 8;                     \
        uint32_t off = (uint32_t)(row * R_ROW + q * 8) * 2;                   \
        CP16(dstb + R_BHI * 2 + off, g_whthi + gs);                           \
        CP16(dstb + R_BLO * 2 + off, g_whtlo + gs);                           \
    }                                                                         \
} while (0)

            R_STAGE(0); CP_COMMIT();

            for (int kc = 0; kc < 8; ++kc) {
                CP_WAIT0();
                __syncthreads();
                if (kc < 7) { R_STAGE(kc + 1); CP_COMMIT(); }

                uint32_t bufb = sbase + (kc & 1) * (R_BUFH * 2);
#pragma unroll
                for (int si = 0; si < 2; ++si) {
                    int s = kh + si * 4;
                    uint32_t koff = (uint32_t)(s * 16 + lcolq) * 2;
                    uint32_t a0 = bufb + (uint32_t)((wm * 32 + lrow) * R_ROW) * 2 + koff;
                    uint32_t a1 = a0 + (uint32_t)(16 * R_ROW) * 2;
                    uint32_t ahi0[4], ahi1[4], alo0[4], alo1[4];
                    ldsm4(ahi0, a0);
                    ldsm4(ahi1, a1);
                    ldsm4(alo0, a0 + (R_ALO - R_AHI) * 2);
                    ldsm4(alo1, a1 + (R_ALO - R_AHI) * 2);
                    uint32_t bb = bufb + R_BHI * 2
                                + (uint32_t)((wn * 16 + lrow) * R_ROW) * 2 + koff;
                    uint32_t bh[4], bl[4];
                    ldsm4(bh, bb);
                    ldsm4(bl, bb + (R_BLO - R_BHI) * 2);

                    mma_bf16(acc[0][0], ahi0, bh[0], bh[2]);
                    mma_bf16(acc[0][1], ahi0, bh[1], bh[3]);
                    mma_bf16(acc[1][0], ahi1, bh[0], bh[2]);
                    mma_bf16(acc[1][1], ahi1, bh[1], bh[3]);
                    mma_bf16(acc[0][0], ahi0, bl[0], bl[2]);
                    mma_bf16(acc[0][1], ahi0, bl[1], bl[3]);
                    mma_bf16(acc[1][0], ahi1, bl[0], bl[2]);
                    mma_bf16(acc[1][1], ahi1, bl[1], bl[3]);
                    mma_bf16(acc[0][0], alo0, bh[0], bh[2]);
                    mma_bf16(acc[0][1], alo0, bh[1], bh[3]);
                    mma_bf16(acc[1][0], alo1, bh[0], bh[2]);
                    mma_bf16(acc[1][1], alo1, bh[1], bh[3]);
                }
                __syncthreads();
            }
#undef R_STAGE
        }

        // store partial sums: part[kh][row][col]
        {
            int prow = wm * 32 + (lane >> 2);
            int pcol = wn * 16 + (lane & 3) * 2;
            float* pb = part + kh * (64 * 36);
#pragma unroll
            for (int f = 0; f < 2; ++f)
#pragma unroll
                for (int nt = 0; nt < 2; ++nt) {
                    float* p = pb + (size_t)(prow + f * 16) * 36 + pcol + nt * 8;
                    p[0] = acc[f][nt][0];
                    p[1] = acc[f][nt][1];
                    p[8 * 36]     = acc[f][nt][2];
                    p[8 * 36 + 1] = acc[f][nt][3];
                }
        }
        __syncthreads();

        // LSTM cell: 1 element/thread; gate order i,f,g,o by chunk
        int nb = (t + 1) & 1;
        {
            float z[4];
#pragma unroll
            for (int c = 0; c < 4; ++c) {
                int lc = c * 8 + ec;
                float s = gxv[c];
#pragma unroll
                for (int p = 0; p < 4; ++p)
                    s += part[p * (64 * 36) + er * 36 + lc];
                z[c] = s;
            }
            float ig = 1.0f / (1.0f + expf(-z[0]));
            float fg = 1.0f / (1.0f + expf(-z[1]));
            float gg = tanhf(z[2]);
            float og = 1.0f / (1.0f + expf(-z[3]));
            float cv = fg * csm[er * 8 + ec] + ig * gg;
            float hv = og * tanhf(cv);
            csm[er * 8 + ec] = cv;
            __nv_bfloat16 hi, lo; bsplit(hv, hi, lo);
            g_hbhi[nb][er][j0h + ec] = hi;
            g_hblo[nb][er][j0h + ec] = lo;
            if (is_last) {
                outp[(size_t)t * (BB * HH) + (size_t)er * HH + j0h + ec] = hv;
            } else {
                size_t o = ((size_t)t * BB + er) * DD + j0h + ec;
                g_ahi[o] = hi;
                g_alo[o] = lo;
            }
        }

        // publish h(t+1): every thread fences its own stores, block syncs,
        // then one thread does the release store of the epoch.
        __threadfence();
        __syncthreads();
        if (tid == 0) {
            asm volatile("st.release.gpu.b32 [%0], %1;"
                         :: "l"(g_hflag + blockIdx.x), "r"((unsigned)(ebase + t + 1))
                         : "memory");
        }
    }
}

// ---------------------------------------------------------------------------
// Host launcher: 1 + 4*(2 preps + gemm + recur) = 17 graph nodes
// Inputs: x [B,T,D], Wx [L,D,4H], Wh [L,H,4H], b [L,4H]. Output [T,B,H] fp32.
// ---------------------------------------------------------------------------
extern "C" void kernel_launch(void* const* d_in, const int* in_sizes, int n_in,
                              void* d_out, int out_size)
{
    const float* x    = (const float*)d_in[0];
    const float* Wx   = (const float*)d_in[1];
    const float* Wh   = (const float*)d_in[2];
    const float* bias = (const float*)d_in[3];
    float* out = (float*)d_out;

    cudaFuncSetAttribute(gemm_tc_kernel,
                         cudaFuncAttributeMaxDynamicSharedMemorySize, G_SMEM);
    cudaFuncSetAttribute(layer_recur_kernel,
                         cudaFuncAttributeMaxDynamicSharedMemorySize, R_SMEM);

    prep_x_kernel<<<MM * DD / 4 / 256, 256>>>(x);

    for (int l = 0; l < LL; ++l) {
        prep_wt_kernel<<<dim3(GG / 32, DD / 32), 256>>>(Wx + (size_t)l * DD * GG, 0);
        prep_wt_kernel<<<dim3(GG / 32, HH / 32), 256>>>(Wh + (size_t)l * HH * GG, 1);

        gemm_tc_kernel<<<dim3(GG / 128, MM / 128), 256, G_SMEM>>>(
            bias + (size_t)l * GG);

        layer_recur_kernel<<<NBLK, 512, R_SMEM>>>(
            out, (l == LL - 1) ? 1 : 0, l * TT);
    }
}